// round 16
// baseline (speedup 1.0000x reference)
#include <cuda_runtime.h>
#include <math_constants.h>

#define FH 64
#define FW 64
#define FC 128
#define NB 2
#define NROI 256
#define OH 7
#define OW 7
#define NBIN (OH * OW)          // 49
#define SCALE 0.0625f
#define C4 (FC / 4)             // 32 float4 per pixel
#define LVL (NB * FH * FW * FC) // floats per pyramid level (4 MB)

// x-max pyramid, NHWC per level: level k = max over columns [x, x+2^k), k=0..3
__device__ float g_pyr[4][LVL];

// ---------------------------------------------------------------------------
// Kernel 1: NCHW -> NHWC transpose + x-max pyramid build.
// One block per (b, y, channel-quarter): 512 blocks, 32ch x 64px tiles.
// ---------------------------------------------------------------------------
__global__ __launch_bounds__(256) void transpose_build(const float* __restrict__ feat) {
    __shared__ float sA[32][FW + 1];         // 8.3 KB
    __shared__ float sB[32][FW + 1];         // 8.3 KB
    int blk = blockIdx.x;                    // 0..511
    int choff = (blk & 3) * 32;              // channel quarter
    int row = blk >> 2;                      // b*64 + y
    int b = row >> 6;
    int y = row & 63;
    int tid = threadIdx.x;

    const float4* src4 = reinterpret_cast<const float4*>(
        feat + (((size_t)b * FC + choff) * FH + y) * FW);
    const size_t cstr4 = (size_t)FH * FW / 4;
    #pragma unroll
    for (int it = 0; it < 2; ++it) {
        int idx = tid + it * 256;            // 0..511
        int c  = idx >> 4;
        int x4 = idx & 15;
        float4 v = src4[(size_t)c * cstr4 + x4];
        sA[c][x4 * 4 + 0] = v.x;
        sA[c][x4 * 4 + 1] = v.y;
        sA[c][x4 * 4 + 2] = v.z;
        sA[c][x4 * 4 + 3] = v.w;
    }
    __syncthreads();

    size_t dbase = (size_t)row * FW * FC + choff;

#define STORE_LEVEL(buf, k)                                                 \
    {                                                                       \
        float* dst = g_pyr[k] + dbase;                                      \
        _Pragma("unroll")                                                   \
        for (int it = 0; it < 2; ++it) {                                    \
            int idx = tid + it * 256;                                       \
            int c4 = idx & 7;                                               \
            int x  = idx >> 3;                                              \
            float4 v;                                                       \
            v.x = buf[c4 * 4 + 0][x];                                       \
            v.y = buf[c4 * 4 + 1][x];                                       \
            v.z = buf[c4 * 4 + 2][x];                                       \
            v.w = buf[c4 * 4 + 3][x];                                       \
            reinterpret_cast<float4*>(dst + (size_t)x * FC)[c4] = v;        \
        }                                                                   \
    }

#define BUILD_LEVEL(dstbuf, srcbuf, step)                                   \
    {                                                                       \
        _Pragma("unroll")                                                   \
        for (int it = 0; it < 8; ++it) {                                    \
            int idx = tid + it * 256;                                       \
            int c = idx >> 6;                                               \
            int x = idx & 63;                                               \
            int x2 = min(x + (step), 63);                                   \
            dstbuf[c][x] = fmaxf(srcbuf[c][x], srcbuf[c][x2]);              \
        }                                                                   \
    }

    STORE_LEVEL(sA, 0)
    BUILD_LEVEL(sB, sA, 1)
    __syncthreads();
    STORE_LEVEL(sB, 1)
    BUILD_LEVEL(sA, sB, 2)
    __syncthreads();
    STORE_LEVEL(sA, 2)
    BUILD_LEVEL(sB, sA, 4)
    __syncthreads();
    STORE_LEVEL(sB, 3)
#undef STORE_LEVEL
#undef BUILD_LEVEL
}

// ---------------------------------------------------------------------------
// Kernel 2: one block (448 thr = 14 warps) per (roi, ph-PAIR): 1024 blocks.
// Warps 0-6 pool stripe ph=2p (bin column = wid); warps 7-13 pool stripe
// ph=2p+1 (bin column = wid-7). x-bounds are shared between the stripes.
// Bin row-segment = 2 pyramid lookups (sparse-table RMQ), R9's dynamic
// unroll-2 loop. PDL overlap as in R15.
// ---------------------------------------------------------------------------
__global__ __launch_bounds__(448, 4) void roipool_kernel(const float* __restrict__ rois,
                                                         float* __restrict__ out) {
    __shared__ float s_acc[14][FC];          // [stripe*7+pw][c] = 7 KB
    __shared__ int s_q[OW][3];               // k, xs0, xs1 per pw (shared!)
    __shared__ int s_geo[6];                 // b, empty, hsA, heA, hsB, heB

    int bx = blockIdx.x;
    int r  = bx >> 2;                        // roi
    int p  = bx & 3;                         // ph-pair index: ph = 2p, 2p+1
    int tid  = threadIdx.x;
    int wid  = tid >> 5;                     // 0..13
    int lane = tid & 31;

    if (tid < OW) {                          // x-bounds: same for both stripes
        int x1 = (int)(rois[r * 5 + 1] * SCALE);
        int x2 = (int)(rois[r * 5 + 3] * SCALE);
        int w = x2 - x1;
        int ws = x1 + (tid * w) / OW;
        int we = x1 + ((tid + 1) * w + OW - 1) / OW;
        int wp = we - ws;
        int k  = (wp > 0) ? (31 - __clz(wp)) : 0;   // wp <= 10 -> k <= 3
        s_q[tid][0] = k;
        s_q[tid][1] = ws;
        s_q[tid][2] = (wp > 0) ? (we - (1 << k)) : ws;
    } else if (tid < 8) {                    // tid == 7: both stripes' rows
        int b  = (int)rois[r * 5 + 0];
        int x1 = (int)(rois[r * 5 + 1] * SCALE);
        int y1 = (int)(rois[r * 5 + 2] * SCALE);
        int x2 = (int)(rois[r * 5 + 3] * SCALE);
        int y2 = (int)(rois[r * 5 + 4] * SCALE);
        int h = y2 - y1;
        int w = x2 - x1;
        int phA = 2 * p;
        int phB = 2 * p + 1;                 // may be 7 (invalid) when p==3
        s_geo[0] = b;
        s_geo[1] = (h <= 0 || w <= 0);
        s_geo[2] = y1 + (phA * h) / OH;
        s_geo[3] = y1 + ((phA + 1) * h + OH - 1) / OH;
        if (phB < OH) {
            s_geo[4] = y1 + (phB * h) / OH;
            s_geo[5] = y1 + ((phB + 1) * h + OH - 1) / OH;
        } else {
            s_geo[4] = 0;
            s_geo[5] = 0;                    // empty range -> loop skipped
        }
    }
    __syncthreads();

    int b     = s_geo[0];
    int empty = s_geo[1];

    // PDL: transpose_build's pyramid writes must be visible past this point.
    cudaGridDependencySynchronize();

    {
        int stripe = (wid >= OW);            // 0 or 1
        int pw  = wid - stripe * OW;         // bin column 0..6
        int hs  = s_geo[2 + 2 * stripe];
        int he  = s_geo[3 + 2 * stripe];
        int k   = s_q[pw][0];
        int xs0 = s_q[pw][1];
        int xs1 = s_q[pw][2];

        float4 acc = make_float4(-CUDART_INF_F, -CUDART_INF_F,
                                 -CUDART_INF_F, -CUDART_INF_F);

        const float4* base = reinterpret_cast<const float4*>(g_pyr[k])
                           + ((size_t)b * FH * FW) * C4 + lane;
        const float4* p0 = base + (size_t)xs0 * C4;
        const float4* p1 = base + (size_t)xs1 * C4;

        #pragma unroll 2
        for (int y = hs; y < he; ++y) {
            size_t ro = (size_t)(y * FW) * C4;
            float4 v0 = p0[ro];              // 2 independent loads per row
            float4 v1 = p1[ro];
            acc.x = fmaxf(acc.x, fmaxf(v0.x, v1.x));
            acc.y = fmaxf(acc.y, fmaxf(v0.y, v1.y));
            acc.z = fmaxf(acc.z, fmaxf(v0.z, v1.z));
            acc.w = fmaxf(acc.w, fmaxf(v0.w, v1.w));
        }
        reinterpret_cast<float4*>(s_acc[wid])[lane] = acc;
    }
    __syncthreads();

    // Epilogue: two 896-float slices out[r][c][ph][pw], ph = 2p (+1).
    // Thread owns (c0 = tid/7 in 0..63, pw = tid%7); 4 iterations:
    // it&1 selects channel half, it>>1 selects stripe.
    int c0 = tid / OW;
    int pw = tid - c0 * OW;
    int phA = 2 * p;
    #pragma unroll
    for (int it = 0; it < 4; ++it) {
        int stripe = it >> 1;
        int ph = phA + stripe;
        if (ph < OH) {
            int c = c0 + (it & 1) * 64;
            float v = s_acc[stripe * OW + pw][c];
            out[(size_t)r * FC * NBIN + c * NBIN + ph * OW + pw]
                = empty ? 0.f : v;
        }
    }
}

extern "C" void kernel_launch(void* const* d_in, const int* in_sizes, int n_in,
                              void* d_out, int out_size) {
    const float* feat = (const float*)d_in[0];   // (2,128,64,64) fp32
    const float* rois = (const float*)d_in[1];   // (256,5) fp32
    float* out = (float*)d_out;                  // (256,128,7,7) fp32

    transpose_build<<<NB * FH * 4, 256>>>(feat);

    // Pool kernel with programmatic dependent launch (implicit completion).
    cudaLaunchConfig_t cfg = {};
    cfg.gridDim  = dim3(NROI * 4);               // (roi, ph-pair)
    cfg.blockDim = dim3(448);
    cfg.stream   = 0;
    cudaLaunchAttribute attrs[1];
    attrs[0].id = cudaLaunchAttributeProgrammaticStreamSerialization;
    attrs[0].val.programmaticStreamSerializationAllowed = 1;
    cfg.attrs = attrs;
    cfg.numAttrs = 1;
    cudaLaunchKernelEx(&cfg, roipool_kernel, rois, out);
}

// round 17
// speedup vs baseline: 1.0078x; 1.0078x over previous
#include <cuda_runtime.h>
#include <math_constants.h>

#define FH 64
#define FW 64
#define FC 128
#define NB 2
#define NROI 256
#define OH 7
#define OW 7
#define NBIN (OH * OW)          // 49
#define SCALE 0.0625f
#define C4 (FC / 4)             // 32 float4 per pixel
#define LVL (NB * FH * FW * FC) // floats per pyramid level (4 MB)

// x-max pyramid, NHWC per level: level k = max over columns [x, x+2^k), k=0..3
__device__ float g_pyr[4][LVL];

// ---------------------------------------------------------------------------
// Kernel 1: NCHW -> NHWC transpose + x-max pyramid build.
// One block per (b, y, 16-channel-slice): 1024 blocks, 16ch x 64px tiles.
// Half the serial work per block vs the 512-block version; better pipelining.
// ---------------------------------------------------------------------------
__global__ __launch_bounds__(256) void transpose_build(const float* __restrict__ feat) {
    __shared__ float sA[16][FW + 1];         // 4.2 KB
    __shared__ float sB[16][FW + 1];         // 4.2 KB
    int blk = blockIdx.x;                    // 0..1023
    int choff = (blk & 7) * 16;              // 16-channel slice
    int row = blk >> 3;                      // b*64 + y
    int b = row >> 6;
    int y = row & 63;
    int tid = threadIdx.x;

    // Phase 1: 256 float4 loads (16 ch x 16 chunks), coalesced along x.
    const float4* src4 = reinterpret_cast<const float4*>(
        feat + (((size_t)b * FC + choff) * FH + y) * FW);
    const size_t cstr4 = (size_t)FH * FW / 4;
    {
        int c  = tid >> 4;                   // 0..15
        int x4 = tid & 15;
        float4 v = src4[(size_t)c * cstr4 + x4];
        sA[c][x4 * 4 + 0] = v.x;
        sA[c][x4 * 4 + 1] = v.y;
        sA[c][x4 * 4 + 2] = v.z;
        sA[c][x4 * 4 + 3] = v.w;
    }
    __syncthreads();

    size_t dbase = (size_t)row * FW * FC + choff;

#define STORE_LEVEL(buf, k)                                                 \
    {                                                                       \
        float* dst = g_pyr[k] + dbase;                                      \
        int c4 = tid & 3;                    /* 4 float4 chunks of 16 ch */ \
        int x  = tid >> 2;                   /* 0..63 */                    \
        float4 v;                                                           \
        v.x = buf[c4 * 4 + 0][x];                                           \
        v.y = buf[c4 * 4 + 1][x];                                           \
        v.z = buf[c4 * 4 + 2][x];                                           \
        v.w = buf[c4 * 4 + 3][x];                                           \
        reinterpret_cast<float4*>(dst + (size_t)x * FC)[c4] = v;            \
    }

#define BUILD_LEVEL(dstbuf, srcbuf, step)                                   \
    {                                                                       \
        _Pragma("unroll")                                                   \
        for (int it = 0; it < 4; ++it) {                                    \
            int idx = tid + it * 256;        /* 0..1023 */                  \
            int c = idx >> 6;                                               \
            int x = idx & 63;                                               \
            int x2 = min(x + (step), 63);                                   \
            dstbuf[c][x] = fmaxf(srcbuf[c][x], srcbuf[c][x2]);              \
        }                                                                   \
    }

    STORE_LEVEL(sA, 0)
    BUILD_LEVEL(sB, sA, 1)                   // level 1 (width 2)
    __syncthreads();
    STORE_LEVEL(sB, 1)
    BUILD_LEVEL(sA, sB, 2)                   // level 2 (width 4)
    __syncthreads();
    STORE_LEVEL(sA, 2)
    BUILD_LEVEL(sB, sA, 4)                   // level 3 (width 8)
    __syncthreads();
    STORE_LEVEL(sB, 3)
#undef STORE_LEVEL
#undef BUILD_LEVEL
}

// ---------------------------------------------------------------------------
// Kernel 2 (R15 exact): one block (224 thr = 7 warps) per (roi, ph) stripe:
// 1792 blocks. Warp = bin column pw; lane = channel chunk. Bin row-segment
// = 2 pyramid lookups (sparse-table RMQ); dynamic y-loop, unroll 2.
// PDL: decode runs during transpose drain; grid-dep sync before pyramid read.
// ---------------------------------------------------------------------------
__global__ __launch_bounds__(224, 8) void roipool_kernel(const float* __restrict__ rois,
                                                         float* __restrict__ out) {
    __shared__ float s_acc[OW][FC];          // 3.5 KB
    __shared__ int s_q[OW][3];               // k, xs0, xs1 per pw
    __shared__ int s_geo[4];                 // b, hs, he, empty

    int bx = blockIdx.x;
    int r  = bx / OH;
    int ph = bx - r * OH;
    int tid  = threadIdx.x;
    int wid  = tid >> 5;                     // == pw (7 warps)
    int lane = tid & 31;

    if (tid < OW) {
        int x1 = (int)(rois[r * 5 + 1] * SCALE);
        int x2 = (int)(rois[r * 5 + 3] * SCALE);
        int w = x2 - x1;
        int ws = x1 + (tid * w) / OW;
        int we = x1 + ((tid + 1) * w + OW - 1) / OW;
        int wp = we - ws;
        int k  = (wp > 0) ? (31 - __clz(wp)) : 0;   // wp <= 10 -> k <= 3
        s_q[tid][0] = k;
        s_q[tid][1] = ws;
        s_q[tid][2] = (wp > 0) ? (we - (1 << k)) : ws;
    } else if (tid < 8) {                    // tid == 7
        int b  = (int)rois[r * 5 + 0];
        int x1 = (int)(rois[r * 5 + 1] * SCALE);
        int y1 = (int)(rois[r * 5 + 2] * SCALE);
        int x2 = (int)(rois[r * 5 + 3] * SCALE);
        int y2 = (int)(rois[r * 5 + 4] * SCALE);
        int h = y2 - y1;
        int w = x2 - x1;
        s_geo[0] = b;
        s_geo[1] = y1 + (ph * h) / OH;
        s_geo[2] = y1 + ((ph + 1) * h + OH - 1) / OH;
        s_geo[3] = (h <= 0 || w <= 0);
    }
    __syncthreads();

    int b  = s_geo[0];
    int hs = s_geo[1];
    int he = s_geo[2];
    int empty = s_geo[3];

    // PDL: transpose_build's pyramid writes must be visible past this point.
    cudaGridDependencySynchronize();

    {
        int k   = s_q[wid][0];
        int xs0 = s_q[wid][1];
        int xs1 = s_q[wid][2];

        float4 acc = make_float4(-CUDART_INF_F, -CUDART_INF_F,
                                 -CUDART_INF_F, -CUDART_INF_F);

        const float4* base = reinterpret_cast<const float4*>(g_pyr[k])
                           + ((size_t)b * FH * FW) * C4 + lane;
        const float4* p0 = base + (size_t)xs0 * C4;
        const float4* p1 = base + (size_t)xs1 * C4;

        #pragma unroll 2
        for (int y = hs; y < he; ++y) {
            size_t ro = (size_t)(y * FW) * C4;
            float4 v0 = p0[ro];              // 2 independent loads per row
            float4 v1 = p1[ro];
            acc.x = fmaxf(acc.x, fmaxf(v0.x, v1.x));
            acc.y = fmaxf(acc.y, fmaxf(v0.y, v1.y));
            acc.z = fmaxf(acc.z, fmaxf(v0.z, v1.z));
            acc.w = fmaxf(acc.w, fmaxf(v0.w, v1.w));
        }
        reinterpret_cast<float4*>(s_acc[wid])[lane] = acc;
    }
    __syncthreads();

    // Epilogue: 896 outputs for this (r, ph) slice: out[r][c][ph][pw].
    float* obase = out + (size_t)r * FC * NBIN + ph * OW;
    int c0 = tid / OW;
    int pw = tid - c0 * OW;
    #pragma unroll
    for (int it = 0; it < 4; ++it) {
        int c = c0 + it * 32;
        obase[c * NBIN + pw] = empty ? 0.f : s_acc[pw][c];
    }
}

extern "C" void kernel_launch(void* const* d_in, const int* in_sizes, int n_in,
                              void* d_out, int out_size) {
    const float* feat = (const float*)d_in[0];   // (2,128,64,64) fp32
    const float* rois = (const float*)d_in[1];   // (256,5) fp32
    float* out = (float*)d_out;                  // (256,128,7,7) fp32

    transpose_build<<<NB * FH * 8, 256>>>(feat);

    // Pool kernel with programmatic dependent launch (implicit completion).
    cudaLaunchConfig_t cfg = {};
    cfg.gridDim  = dim3(NROI * OH);
    cfg.blockDim = dim3(224);
    cfg.stream   = 0;
    cudaLaunchAttribute attrs[1];
    attrs[0].id = cudaLaunchAttributeProgrammaticStreamSerialization;
    attrs[0].val.programmaticStreamSerializationAllowed = 1;
    cfg.attrs = attrs;
    cfg.numAttrs = 1;
    cudaLaunchKernelEx(&cfg, roipool_kernel, rois, out);
}